// round 15
// baseline (speedup 1.0000x reference)
#include <cuda_runtime.h>
#include <cuda_fp16.h>
#include <math.h>

#define POOL 7

// fp16 copy of the feature map: 64*64*1024 halves = 8.4 MB (static scratch,
// allocation-free per harness rules). Stored as uint2 = 4 halves = 4 channels.
#define MAX_FEAT_U2 (64 * 64 * 1024 / 4)
__device__ uint2 g_feat_h[MAX_FEAT_U2];

__device__ __forceinline__ float read_stride(const void* p) {
    int iv = *(const int*)p;
    if (iv >= 1 && iv <= 65536) return (float)iv;
    return *(const float*)p;
}

__device__ __forceinline__ float4 lerp4(float4 a, float4 b, float t) {
    float4 r;
    r.x = a.x + (b.x - a.x) * t;
    r.y = a.y + (b.y - a.y) * t;
    r.z = a.z + (b.z - a.z) * t;
    r.w = a.w + (b.w - a.w) * t;
    return r;
}

__device__ __forceinline__ float4 u2_to_f4(uint2 u) {
    __half2 lo = *reinterpret_cast<__half2*>(&u.x);
    __half2 hi = *reinterpret_cast<__half2*>(&u.y);
    float2 l = __half22float2(lo);
    float2 h = __half22float2(hi);
    return make_float4(l.x, l.y, h.x, h.y);
}

// Pass 1: fp32 feature -> fp16 (one float4 -> one uint2 per thread).
__global__ void __launch_bounds__(256)
convert_kernel(const float4* __restrict__ feat, int n4) {
    int i = blockIdx.x * blockDim.x + threadIdx.x;
    if (i < n4) {
        float4 v = feat[i];
        __half2 lo = __floats2half2_rn(v.x, v.y);
        __half2 hi = __floats2half2_rn(v.z, v.w);
        uint2 u;
        u.x = *reinterpret_cast<unsigned*>(&lo);
        u.y = *reinterpret_cast<unsigned*>(&hi);
        g_feat_h[i] = u;
    }
}

// Pass 2: exact R3 structure (proven at the LTS cap), taps read as fp16
// (half the read bytes), all arithmetic in fp32.
// One block per (roi, py); 256 threads, each owns 4 channels (one uint2).
__global__ void __launch_bounds__(256)
roi_pool_kernel(const float* __restrict__ rois,
                const void* __restrict__ stride_p,
                float* __restrict__ out,
                int W, int C4) {
    const int py = blockIdx.x;     // 0..6
    const int n  = blockIdx.y;     // roi
    const int c  = threadIdx.x;    // 4-channel lane 0..C4-1

    // ---- uniform coordinate math ----
    const float s = read_stride(stride_p);
    const int ymin = (int)(rois[4 * n + 0] / s);
    const int xmin = (int)(rois[4 * n + 1] / s);
    const int ymax = (int)(rois[4 * n + 2] / s);
    const int xmax = (int)(rois[4 * n + 3] / s);

    const int   spany = ymax - ymin;
    const float sy    = (float)(spany + 1) / (float)POOL;
    const float srcy  = (float)py * sy;
    const int   iy0   = (int)floorf(srcy);
    const float dy    = srcy - (float)iy0;
    const int   y0    = ymin + iy0;
    const int   y1    = ymin + min(iy0 + 1, spany);

    const int   spanx = xmax - xmin;
    const float sx    = (float)(spanx + 1) / (float)POOL;
    int   nx0[POOL], nx1[POOL];
    float dxv[POOL];
#pragma unroll
    for (int px = 0; px < POOL; ++px) {
        const float srcx = (float)px * sx;
        const int   ix0  = (int)floorf(srcx);
        dxv[px] = srcx - (float)ix0;
        nx0[px] = xmin + ix0;
        nx1[px] = xmin + min(ix0 + 1, spanx);
    }

    const uint2* __restrict__ row0 = g_feat_h + y0 * W * C4 + c;
    const uint2* __restrict__ row1 = g_feat_h + y1 * W * C4 + c;
    float4* __restrict__ o = (float4*)out + (n * (POOL * POOL) + py * POOL) * C4 + c;

    // sliding cache of y-blended columns (fp32)
    int cA = -1, cB = -1;
    float4 vA, vB;

#pragma unroll
    for (int px = 0; px < POOL; ++px) {
        const int   x0 = nx0[px];
        const int   x1 = nx1[px];
        const float dx = dxv[px];

        if (x0 != cA) {                    // warp-uniform branches
            if (x0 == cB) { vA = vB; }
            else {
                const float4 t0 = u2_to_f4(row0[x0 * C4]);
                const float4 t1 = u2_to_f4(row1[x0 * C4]);
                vA = lerp4(t0, t1, dy);
            }
            cA = x0;
        }
        if (x1 != cB) {
            if (x1 == cA) { vB = vA; }
            else {
                const float4 t0 = u2_to_f4(row0[x1 * C4]);
                const float4 t1 = u2_to_f4(row1[x1 * C4]);
                vB = lerp4(t0, t1, dy);
            }
            cB = x1;
        }

        o[px * C4] = lerp4(vA, vB, dx);
    }
}

extern "C" void kernel_launch(void* const* d_in, const int* in_sizes, int n_in,
                              void* d_out, int out_size) {
    const float* feat  = (const float*)d_in[0];   // (1, H, W, C) fp32
    const float* rois  = (const float*)d_in[1];   // (N, 4) fp32
    const void*  strid = d_in[2];                 // scalar

    int N = in_sizes[1] / 4;
    int C = out_size / (N * POOL * POOL);         // 1024
    int HW = in_sizes[0] / C;                     // 4096
    int W = 1;
    while (W * W < HW) W <<= 1;                   // 64
    if (W * W != HW) {
        W = (int)(sqrtf((float)HW) + 0.5f);
    }
    int C4 = C / 4;                               // 256

    // Pass 1: fp32 -> fp16 staging (8.4 MB)
    int n4 = in_sizes[0] / 4;                     // 1,048,576 float4s
    convert_kernel<<<(n4 + 255) / 256, 256>>>((const float4*)feat, n4);

    // Pass 2: pooling from fp16 staging
    dim3 grid(POOL, N);
    roi_pool_kernel<<<grid, 256>>>(rois, strid, (float*)d_out, W, C4);
}